// round 1
// baseline (speedup 1.0000x reference)
#include <cuda_runtime.h>

#define DD 128
#define NMAX 50000
#define LAYERS 3
#define EPSV 1e-5f

// ---- scratch (no allocs allowed) ----
__device__ float g_m[NMAX * DD];     // m = h @ W
__device__ float g_agg[NMAX * DD];   // aggregated messages
__device__ float g_h[NMAX * DD];     // layer output (ping buffer)
__device__ float g_dinv[NMAX];       // deg -> rsqrt(deg)
__device__ float g_sum[DD];
__device__ float g_sumsq[DD];
__device__ float g_scale[DD];
__device__ float g_shift[DD];

// ---------------- degree ----------------
__global__ void deg_init_kernel(int n) {
    int i = blockIdx.x * blockDim.x + threadIdx.x;
    if (i < n) g_dinv[i] = 1.0f;  // self-loop contributes 1
}

__global__ void deg_count_kernel(const int* __restrict__ dst, int E) {
    int e = blockIdx.x * blockDim.x + threadIdx.x;
    if (e < E) atomicAdd(&g_dinv[dst[e]], 1.0f);
}

__global__ void deg_rsqrt_kernel(int n) {
    int i = blockIdx.x * blockDim.x + threadIdx.x;
    if (i < n) g_dinv[i] = rsqrtf(g_dinv[i]);
}

// ---------------- GEMM: m[n,j] = sum_k h[n,k] * W[k,j] ----------------
// Block computes 32 rows x 128 cols. 256 threads: col = tid&127, row half = tid>>7.
__global__ __launch_bounds__(256) void gemm_kernel(
    const float* __restrict__ x, int use_x,
    const float* __restrict__ Wl, int n)
{
    const float* __restrict__ h = use_x ? x : g_h;
    __shared__ float hs[32][33];   // 32 rows x 32 k (padded)
    __shared__ float ws[32][DD];   // 32 k x 128 j

    int tid = threadIdx.x;
    int j = tid & 127;
    int rhalf = tid >> 7;          // 0 or 1
    int row0 = blockIdx.x * 32;

    float acc[16];
#pragma unroll
    for (int r = 0; r < 16; r++) acc[r] = 0.0f;

    for (int kt = 0; kt < DD; kt += 32) {
        // load 32x32 h tile
        for (int i = tid; i < 32 * 32; i += 256) {
            int r = i >> 5, c = i & 31;
            int gr = row0 + r;
            hs[r][c] = (gr < n) ? h[(size_t)gr * DD + kt + c] : 0.0f;
        }
        // load 32x128 W tile
        for (int i = tid; i < 32 * DD; i += 256) {
            int r = i >> 7, c = i & 127;
            ws[r][c] = Wl[(size_t)(kt + r) * DD + c];
        }
        __syncthreads();
#pragma unroll
        for (int kk = 0; kk < 32; kk++) {
            float wv = ws[kk][j];
#pragma unroll
            for (int r = 0; r < 16; r++)
                acc[r] += hs[rhalf * 16 + r][kk] * wv;
        }
        __syncthreads();
    }
#pragma unroll
    for (int r = 0; r < 16; r++) {
        int gr = row0 + rhalf * 16 + r;
        if (gr < n) g_m[(size_t)gr * DD + j] = acc[r];
    }
}

// ---------------- self-loop init: agg[v,:] = dinv[v]^2 * m[v,:] ----------------
__global__ void selfloop_kernel(int n) {
    int idx = blockIdx.x * blockDim.x + threadIdx.x;  // float4 index
    int total = n * (DD / 4);
    if (idx >= total) return;
    int row = idx >> 5;                // idx / (128/4)
    float di = g_dinv[row];
    float w = di * di;
    float4 v = reinterpret_cast<const float4*>(g_m)[idx];
    reinterpret_cast<float4*>(g_agg)[idx] =
        make_float4(v.x * w, v.y * w, v.z * w, v.w * w);
}

// ---------------- edge scatter: agg[dst,:] += dinv[src]*dinv[dst] * m[src,:] ----
// one warp per edge; lane handles one float4 (4*32 = 128 cols)
__global__ __launch_bounds__(256) void scatter_kernel(
    const int* __restrict__ src, const int* __restrict__ dst, int E)
{
    int warp = (blockIdx.x * blockDim.x + threadIdx.x) >> 5;
    int lane = threadIdx.x & 31;
    if (warp >= E) return;
    int s = src[warp];
    int t = dst[warp];
    float w = g_dinv[s] * g_dinv[t];
    float4 v = reinterpret_cast<const float4*>(g_m + (size_t)s * DD)[lane];
    float* p = g_agg + (size_t)t * DD + lane * 4;
    asm volatile("red.global.add.v4.f32 [%0], {%1, %2, %3, %4};"
                 :: "l"(p), "f"(v.x * w), "f"(v.y * w), "f"(v.z * w), "f"(v.w * w)
                 : "memory");
}

// ---------------- batchnorm stats ----------------
__global__ void zero_stats_kernel() {
    int d = threadIdx.x;
    g_sum[d] = 0.0f;
    g_sumsq[d] = 0.0f;
}

__global__ __launch_bounds__(DD) void stats_kernel(int n) {
    int col = threadIdx.x;  // 128 threads = 128 cols, coalesced row reads
    float s = 0.0f, sq = 0.0f;
    for (int r = blockIdx.x; r < n; r += gridDim.x) {
        float v = g_agg[(size_t)r * DD + col];
        s += v;
        sq += v * v;
    }
    atomicAdd(&g_sum[col], s);
    atomicAdd(&g_sumsq[col], sq);
}

// bias b cancels inside BN (mean shifts by b, variance unchanged) -> skip it.
__global__ void finalize_stats_kernel(const float* __restrict__ gamma,
                                      const float* __restrict__ beta, float inv_n) {
    int d = threadIdx.x;
    float mu = g_sum[d] * inv_n;
    float var = g_sumsq[d] * inv_n - mu * mu;
    float rstd = rsqrtf(var + EPSV);
    float sc = gamma[d] * rstd;
    g_scale[d] = sc;
    g_shift[d] = beta[d] - mu * sc;
}

// ---------------- normalize + relu ----------------
__global__ void norm_relu_kernel(float* __restrict__ out_ext, int use_ext, int n) {
    float* __restrict__ out = use_ext ? out_ext : g_h;
    int idx = blockIdx.x * blockDim.x + threadIdx.x;  // float4 index
    int total = n * (DD / 4);
    if (idx >= total) return;
    int c4 = (idx & 31) * 4;
    float4 v = reinterpret_cast<const float4*>(g_agg)[idx];
    float4 r;
    r.x = fmaxf(0.0f, v.x * g_scale[c4 + 0] + g_shift[c4 + 0]);
    r.y = fmaxf(0.0f, v.y * g_scale[c4 + 1] + g_shift[c4 + 1]);
    r.z = fmaxf(0.0f, v.z * g_scale[c4 + 2] + g_shift[c4 + 2]);
    r.w = fmaxf(0.0f, v.w * g_scale[c4 + 3] + g_shift[c4 + 3]);
    reinterpret_cast<float4*>(out)[idx] = r;
}

// ---------------- launcher ----------------
extern "C" void kernel_launch(void* const* d_in, const int* in_sizes, int n_in,
                              void* d_out, int out_size) {
    const float* x     = (const float*)d_in[0];
    const int*   ei    = (const int*)d_in[1];
    const float* W     = (const float*)d_in[2];
    // d_in[3] = b : mathematically absorbed by batchnorm, unused
    const float* gamma = (const float*)d_in[4];
    const float* beta  = (const float*)d_in[5];
    float* out = (float*)d_out;

    int n = in_sizes[0] / DD;
    int E = in_sizes[1] / 2;
    const int* src = ei;
    const int* dst = ei + E;

    deg_init_kernel<<<(n + 255) / 256, 256>>>(n);
    deg_count_kernel<<<(E + 255) / 256, 256>>>(dst, E);
    deg_rsqrt_kernel<<<(n + 255) / 256, 256>>>(n);

    int elem4 = n * (DD / 4);
    for (int l = 0; l < LAYERS; l++) {
        gemm_kernel<<<(n + 31) / 32, 256>>>(x, (l == 0) ? 1 : 0,
                                            W + (size_t)l * DD * DD, n);
        selfloop_kernel<<<(elem4 + 255) / 256, 256>>>(n);
        scatter_kernel<<<(E + 7) / 8, 256>>>(src, dst, E);
        zero_stats_kernel<<<1, DD>>>();
        stats_kernel<<<512, DD>>>(n);
        finalize_stats_kernel<<<1, DD>>>(gamma + (size_t)l * DD,
                                         beta + (size_t)l * DD, 1.0f / (float)n);
        norm_relu_kernel<<<(elem4 + 255) / 256, 256>>>(out, (l == LAYERS - 1) ? 1 : 0, n);
    }
}

// round 4
// speedup vs baseline: 1.3527x; 1.3527x over previous
#include <cuda_runtime.h>

#define DD 128
#define NMAX 50000
#define EMAX 800000
#define LAYERS 3
#define EPSV 1e-5f

// ---- scratch (no allocs allowed) ----
__device__ float g_m[NMAX * DD];     // m = h @ W
__device__ float g_agg[NMAX * DD];   // aggregated messages (pre-BN)
__device__ float g_h[NMAX * DD];     // layer activation buffer
__device__ float g_dinv[NMAX];       // rsqrt(deg)
__device__ int   g_cnt[NMAX];        // in-edge count per dst (no self-loop)
__device__ int   g_off[NMAX];        // per-node segment start (unordered alloc)
__device__ int   g_cur[NMAX];        // scatter cursors
__device__ int   g_total;            // segment allocator
__device__ int   g_es[EMAX];         // dst-grouped src ids
__device__ float g_ew[EMAX];         // dst-grouped edge weights dinv[s]*dinv[t]
__device__ float g_sum[DD];
__device__ float g_sumsq[DD];
__device__ float g_scale[DD];
__device__ float g_shift[DD];

// ---------------- CSR construction ----------------
__global__ void zero_cnt_kernel(int n) {
    int i = blockIdx.x * blockDim.x + threadIdx.x;
    if (i < n) g_cnt[i] = 0;
    if (i == 0) g_total = 0;
}

__global__ void hist_kernel(const int* __restrict__ dst, int E) {
    int e = blockIdx.x * blockDim.x + threadIdx.x;
    if (e < E) atomicAdd(&g_cnt[dst[e]], 1);
}

__global__ void dinv_kernel(int n) {
    int i = blockIdx.x * blockDim.x + threadIdx.x;
    if (i < n) g_dinv[i] = rsqrtf((float)(g_cnt[i] + 1));  // +1 self-loop
}

// unordered segment allocation: each node grabs cnt slots. Gather only needs
// per-node contiguity, not global ordering.
__global__ void alloc_off_kernel(int n) {
    int i = blockIdx.x * blockDim.x + threadIdx.x;
    if (i >= n) return;
    int c = g_cnt[i];
    int pos = (c > 0) ? atomicAdd(&g_total, c) : 0;
    g_off[i] = pos;
    g_cur[i] = pos;
}

__global__ void edge_sort_kernel(const int* __restrict__ src,
                                 const int* __restrict__ dst, int E) {
    int e = blockIdx.x * blockDim.x + threadIdx.x;
    if (e >= E) return;
    int s = src[e], t = dst[e];
    int pos = atomicAdd(&g_cur[t], 1);
    g_es[pos] = s;
    g_ew[pos] = g_dinv[s] * g_dinv[t];
}

// ---------------- GEMM (round-1 proven version, verbatim) ----------------
__global__ __launch_bounds__(256) void gemm_kernel(
    const float* __restrict__ x, int use_x,
    const float* __restrict__ Wl, int n)
{
    const float* __restrict__ h = use_x ? x : g_h;
    __shared__ float hs[32][33];   // 32 rows x 32 k (padded)
    __shared__ float ws[32][DD];   // 32 k x 128 j

    int tid = threadIdx.x;
    int j = tid & 127;
    int rhalf = tid >> 7;          // 0 or 1
    int row0 = blockIdx.x * 32;

    float acc[16];
#pragma unroll
    for (int r = 0; r < 16; r++) acc[r] = 0.0f;

    for (int kt = 0; kt < DD; kt += 32) {
        for (int i = tid; i < 32 * 32; i += 256) {
            int r = i >> 5, c = i & 31;
            int gr = row0 + r;
            hs[r][c] = (gr < n) ? h[(size_t)gr * DD + kt + c] : 0.0f;
        }
        for (int i = tid; i < 32 * DD; i += 256) {
            int r = i >> 7, c = i & 127;
            ws[r][c] = Wl[(size_t)(kt + r) * DD + c];
        }
        __syncthreads();
#pragma unroll
        for (int kk = 0; kk < 32; kk++) {
            float wv = ws[kk][j];
#pragma unroll
            for (int r = 0; r < 16; r++)
                acc[r] += hs[rhalf * 16 + r][kk] * wv;
        }
        __syncthreads();
    }
#pragma unroll
    for (int r = 0; r < 16; r++) {
        int gr = row0 + rhalf * 16 + r;
        if (gr < n) g_m[(size_t)gr * DD + j] = acc[r];
    }
}

// ---------------- gather: agg[t,:] = dinv[t]^2*m[t,:] + sum_e w_e*m[src_e,:] ----
__global__ __launch_bounds__(256) void gather_kernel(int n) {
    int node = (blockIdx.x * blockDim.x + threadIdx.x) >> 5;
    int lane = threadIdx.x & 31;
    if (node >= n) return;
    const float4* __restrict__ m4 = (const float4*)g_m;

    float di = g_dinv[node];
    float w0 = di * di;
    float4 acc = m4[(size_t)node * 32 + lane];
    acc.x *= w0; acc.y *= w0; acc.z *= w0; acc.w *= w0;

    int beg = g_off[node];
    int cnt = g_cnt[node];
    for (int i = 0; i < cnt; i++) {
        int s = g_es[beg + i];
        float w = g_ew[beg + i];
        float4 v = m4[(size_t)s * 32 + lane];
        acc.x += w * v.x;
        acc.y += w * v.y;
        acc.z += w * v.z;
        acc.w += w * v.w;
    }
    ((float4*)g_agg)[(size_t)node * 32 + lane] = acc;
}

// ---------------- batchnorm stats (round-1 proven) ----------------
__global__ void zero_stats_kernel() {
    int d = threadIdx.x;
    g_sum[d] = 0.0f;
    g_sumsq[d] = 0.0f;
}

__global__ __launch_bounds__(DD) void stats_kernel(int n) {
    int col = threadIdx.x;
    float s = 0.0f, sq = 0.0f;
    for (int r = blockIdx.x; r < n; r += gridDim.x) {
        float v = g_agg[(size_t)r * DD + col];
        s += v;
        sq += v * v;
    }
    atomicAdd(&g_sum[col], s);
    atomicAdd(&g_sumsq[col], sq);
}

// GCN bias b cancels inside BN (mean shifts by b, variance unchanged) -> skip it.
__global__ void finalize_stats_kernel(const float* __restrict__ gamma,
                                      const float* __restrict__ beta, float inv_n) {
    int d = threadIdx.x;
    float mu = g_sum[d] * inv_n;
    float var = g_sumsq[d] * inv_n - mu * mu;
    float rstd = rsqrtf(var + EPSV);
    float sc = gamma[d] * rstd;
    g_scale[d] = sc;
    g_shift[d] = beta[d] - mu * sc;
}

// ---------------- normalize + relu (round-1 proven) ----------------
__global__ void norm_relu_kernel(float* __restrict__ out_ext, int use_ext, int n) {
    float* __restrict__ out = use_ext ? out_ext : g_h;
    int idx = blockIdx.x * blockDim.x + threadIdx.x;  // float4 index
    int total = n * (DD / 4);
    if (idx >= total) return;
    int c4 = (idx & 31) * 4;
    float4 v = reinterpret_cast<const float4*>(g_agg)[idx];
    float4 r;
    r.x = fmaxf(0.0f, v.x * g_scale[c4 + 0] + g_shift[c4 + 0]);
    r.y = fmaxf(0.0f, v.y * g_scale[c4 + 1] + g_shift[c4 + 1]);
    r.z = fmaxf(0.0f, v.z * g_scale[c4 + 2] + g_shift[c4 + 2]);
    r.w = fmaxf(0.0f, v.w * g_scale[c4 + 3] + g_shift[c4 + 3]);
    reinterpret_cast<float4*>(out)[idx] = r;
}

// ---------------- launcher ----------------
extern "C" void kernel_launch(void* const* d_in, const int* in_sizes, int n_in,
                              void* d_out, int out_size) {
    const float* x     = (const float*)d_in[0];
    const int*   ei    = (const int*)d_in[1];
    const float* W     = (const float*)d_in[2];
    // d_in[3] = b : mathematically absorbed by batchnorm, unused
    const float* gamma = (const float*)d_in[4];
    const float* beta  = (const float*)d_in[5];
    float* out = (float*)d_out;

    int n = in_sizes[0] / DD;
    int E = in_sizes[1] / 2;
    const int* src = ei;
    const int* dst = ei + E;

    // CSR build (once per launch)
    zero_cnt_kernel<<<(n + 255) / 256, 256>>>(n);
    hist_kernel<<<(E + 255) / 256, 256>>>(dst, E);
    dinv_kernel<<<(n + 255) / 256, 256>>>(n);
    alloc_off_kernel<<<(n + 255) / 256, 256>>>(n);
    edge_sort_kernel<<<(E + 255) / 256, 256>>>(src, dst, E);

    int elem4 = n * (DD / 4);
    for (int l = 0; l < LAYERS; l++) {
        gemm_kernel<<<(n + 31) / 32, 256>>>(x, (l == 0) ? 1 : 0,
                                            W + (size_t)l * DD * DD, n);
        gather_kernel<<<(n + 7) / 8, 256>>>(n);
        zero_stats_kernel<<<1, DD>>>();
        stats_kernel<<<512, DD>>>(n);
        finalize_stats_kernel<<<1, DD>>>(gamma + (size_t)l * DD,
                                         beta + (size_t)l * DD, 1.0f / (float)n);
        norm_relu_kernel<<<(elem4 + 255) / 256, 256>>>(out, (l == LAYERS - 1) ? 1 : 0, n);
    }
}

// round 5
// speedup vs baseline: 1.8359x; 1.3572x over previous
#include <cuda_runtime.h>

#define DD 128
#define NMAX 50000
#define EMAX 800000
#define LAYERS 3
#define EPSV 1e-5f

// ---- scratch (no allocs allowed) ----
__device__ float g_m[NMAX * DD];     // m = h @ W
__device__ float g_agg[NMAX * DD];   // aggregated messages (pre-BN)
__device__ float g_h[NMAX * DD];     // layer activation buffer
__device__ float g_dinv[NMAX];       // rsqrt(deg)
__device__ int   g_cnt[NMAX];        // in-edge count per dst (no self-loop)
__device__ int   g_off[NMAX];        // per-node segment start (unordered alloc)
__device__ int   g_cur[NMAX];        // scatter cursors
__device__ int   g_total;            // segment allocator
__device__ int   g_es[EMAX];         // dst-grouped src ids
__device__ float g_ew[EMAX];         // dst-grouped edge weights dinv[s]*dinv[t]
__device__ float g_sum[DD];
__device__ float g_sumsq[DD];
__device__ float g_scale[DD];
__device__ float g_shift[DD];

// ---------------- CSR construction (round-4 proven) ----------------
__global__ void zero_cnt_kernel(int n) {
    int i = blockIdx.x * blockDim.x + threadIdx.x;
    if (i < n) g_cnt[i] = 0;
    if (i == 0) g_total = 0;
}

__global__ void hist_kernel(const int* __restrict__ dst, int E) {
    int e = blockIdx.x * blockDim.x + threadIdx.x;
    if (e < E) atomicAdd(&g_cnt[dst[e]], 1);
}

__global__ void dinv_kernel(int n) {
    int i = blockIdx.x * blockDim.x + threadIdx.x;
    if (i < n) g_dinv[i] = rsqrtf((float)(g_cnt[i] + 1));  // +1 self-loop
}

__global__ void alloc_off_kernel(int n) {
    int i = blockIdx.x * blockDim.x + threadIdx.x;
    if (i >= n) return;
    int c = g_cnt[i];
    int pos = (c > 0) ? atomicAdd(&g_total, c) : 0;
    g_off[i] = pos;
    g_cur[i] = pos;
}

__global__ void edge_sort_kernel(const int* __restrict__ src,
                                 const int* __restrict__ dst, int E) {
    int e = blockIdx.x * blockDim.x + threadIdx.x;
    if (e >= E) return;
    int s = src[e], t = dst[e];
    int pos = atomicAdd(&g_cur[t], 1);
    g_es[pos] = s;
    g_ew[pos] = g_dinv[s] * g_dinv[t];
}

// ---------------- GEMM: m[n,j] = sum_k h[n,k] * W[k,j] ----------------
// 64 rows x 128 cols per block, 256 threads, 8x4 register micro-tile.
// Inner loop per thread: 3 LDS.128 -> 32 FFMA.
__global__ __launch_bounds__(256) void gemm_kernel(
    const float* __restrict__ x, int use_x,
    const float* __restrict__ Wl, int n)
{
    const float* __restrict__ in = use_x ? x : g_h;
    __shared__ float hsT[32][64];      // [k][row] transposed tile
    __shared__ float ws[32][DD];       // [k][col]

    int tid = threadIdx.x;
    int row0 = blockIdx.x * 64;
    int c4 = tid & 31;   // col quad: cols c4*4 .. c4*4+3 (lane id)
    int rg = tid >> 5;   // row group: rows rg*8 .. rg*8+7 (warp id)

    float acc[8][4];
#pragma unroll
    for (int r = 0; r < 8; r++)
#pragma unroll
        for (int c = 0; c < 4; c++) acc[r][c] = 0.0f;

    for (int kt = 0; kt < DD; kt += 32) {
        // h tile: 64 rows x 32 k, stored transposed. 512 float4 loads.
        for (int q = tid; q < 512; q += 256) {
            int kq = q >> 6, row = q & 63;
            int gr = row0 + row;
            float4 v = make_float4(0.f, 0.f, 0.f, 0.f);
            if (gr < n)
                v = *(const float4*)(in + (size_t)gr * DD + kt + kq * 4);
            hsT[kq * 4 + 0][row] = v.x;
            hsT[kq * 4 + 1][row] = v.y;
            hsT[kq * 4 + 2][row] = v.z;
            hsT[kq * 4 + 3][row] = v.w;
        }
        // W tile: 32 k x 128 cols, coalesced float4 loads.
        for (int q = tid; q < 1024; q += 256) {
            int r = q >> 5, cq = q & 31;
            *(float4*)&ws[r][cq * 4] =
                *(const float4*)(Wl + (size_t)(kt + r) * DD + cq * 4);
        }
        __syncthreads();
#pragma unroll
        for (int kk = 0; kk < 32; kk++) {
            float4 b = *(float4*)&ws[kk][c4 * 4];
            float4 a0 = *(float4*)&hsT[kk][rg * 8];
            float4 a1 = *(float4*)&hsT[kk][rg * 8 + 4];
            float a[8] = {a0.x, a0.y, a0.z, a0.w, a1.x, a1.y, a1.z, a1.w};
#pragma unroll
            for (int r = 0; r < 8; r++) {
                acc[r][0] += a[r] * b.x;
                acc[r][1] += a[r] * b.y;
                acc[r][2] += a[r] * b.z;
                acc[r][3] += a[r] * b.w;
            }
        }
        __syncthreads();
    }
#pragma unroll
    for (int r = 0; r < 8; r++) {
        int gr = row0 + rg * 8 + r;
        if (gr < n) {
            float4 v = make_float4(acc[r][0], acc[r][1], acc[r][2], acc[r][3]);
            *(float4*)(g_m + (size_t)gr * DD + c4 * 4) = v;
        }
    }
}

// ---------------- gather (round-4 proven) ----------------
__global__ __launch_bounds__(256) void gather_kernel(int n) {
    int node = (blockIdx.x * blockDim.x + threadIdx.x) >> 5;
    int lane = threadIdx.x & 31;
    if (node >= n) return;
    const float4* __restrict__ m4 = (const float4*)g_m;

    float di = g_dinv[node];
    float w0 = di * di;
    float4 acc = m4[(size_t)node * 32 + lane];
    acc.x *= w0; acc.y *= w0; acc.z *= w0; acc.w *= w0;

    int beg = g_off[node];
    int cnt = g_cnt[node];
    for (int i = 0; i < cnt; i++) {
        int s = g_es[beg + i];
        float w = g_ew[beg + i];
        float4 v = m4[(size_t)s * 32 + lane];
        acc.x += w * v.x;
        acc.y += w * v.y;
        acc.z += w * v.z;
        acc.w += w * v.w;
    }
    ((float4*)g_agg)[(size_t)node * 32 + lane] = acc;
}

// ---------------- batchnorm stats (round-4 proven) ----------------
__global__ void zero_stats_kernel() {
    int d = threadIdx.x;
    g_sum[d] = 0.0f;
    g_sumsq[d] = 0.0f;
}

__global__ __launch_bounds__(DD) void stats_kernel(int n) {
    int col = threadIdx.x;
    float s = 0.0f, sq = 0.0f;
    for (int r = blockIdx.x; r < n; r += gridDim.x) {
        float v = g_agg[(size_t)r * DD + col];
        s += v;
        sq += v * v;
    }
    atomicAdd(&g_sum[col], s);
    atomicAdd(&g_sumsq[col], sq);
}

// GCN bias b cancels inside BN (mean shifts by b, variance unchanged) -> skip it.
__global__ void finalize_stats_kernel(const float* __restrict__ gamma,
                                      const float* __restrict__ beta, float inv_n) {
    int d = threadIdx.x;
    float mu = g_sum[d] * inv_n;
    float var = g_sumsq[d] * inv_n - mu * mu;
    float rstd = rsqrtf(var + EPSV);
    float sc = gamma[d] * rstd;
    g_scale[d] = sc;
    g_shift[d] = beta[d] - mu * sc;
}

// ---------------- normalize + relu (round-4 proven) ----------------
__global__ void norm_relu_kernel(float* __restrict__ out_ext, int use_ext, int n) {
    float* __restrict__ out = use_ext ? out_ext : g_h;
    int idx = blockIdx.x * blockDim.x + threadIdx.x;  // float4 index
    int total = n * (DD / 4);
    if (idx >= total) return;
    int c4 = (idx & 31) * 4;
    float4 v = reinterpret_cast<const float4*>(g_agg)[idx];
    float4 r;
    r.x = fmaxf(0.0f, v.x * g_scale[c4 + 0] + g_shift[c4 + 0]);
    r.y = fmaxf(0.0f, v.y * g_scale[c4 + 1] + g_shift[c4 + 1]);
    r.z = fmaxf(0.0f, v.z * g_scale[c4 + 2] + g_shift[c4 + 2]);
    r.w = fmaxf(0.0f, v.w * g_scale[c4 + 3] + g_shift[c4 + 3]);
    reinterpret_cast<float4*>(out)[idx] = r;
}

// ---------------- launcher ----------------
extern "C" void kernel_launch(void* const* d_in, const int* in_sizes, int n_in,
                              void* d_out, int out_size) {
    const float* x     = (const float*)d_in[0];
    const int*   ei    = (const int*)d_in[1];
    const float* W     = (const float*)d_in[2];
    // d_in[3] = b : mathematically absorbed by batchnorm, unused
    const float* gamma = (const float*)d_in[4];
    const float* beta  = (const float*)d_in[5];
    float* out = (float*)d_out;

    int n = in_sizes[0] / DD;
    int E = in_sizes[1] / 2;
    const int* src = ei;
    const int* dst = ei + E;

    // CSR build (once per launch)
    zero_cnt_kernel<<<(n + 255) / 256, 256>>>(n);
    hist_kernel<<<(E + 255) / 256, 256>>>(dst, E);
    dinv_kernel<<<(n + 255) / 256, 256>>>(n);
    alloc_off_kernel<<<(n + 255) / 256, 256>>>(n);
    edge_sort_kernel<<<(E + 255) / 256, 256>>>(src, dst, E);

    int elem4 = n * (DD / 4);
    for (int l = 0; l < LAYERS; l++) {
        gemm_kernel<<<(n + 63) / 64, 256>>>(x, (l == 0) ? 1 : 0,
                                            W + (size_t)l * DD * DD, n);
        gather_kernel<<<(n + 7) / 8, 256>>>(n);
        zero_stats_kernel<<<1, DD>>>();
        stats_kernel<<<512, DD>>>(n);
        finalize_stats_kernel<<<1, DD>>>(gamma + (size_t)l * DD,
                                         beta + (size_t)l * DD, 1.0f / (float)n);
        norm_relu_kernel<<<(elem4 + 255) / 256, 256>>>(out, (l == LAYERS - 1) ? 1 : 0, n);
    }
}

// round 7
// speedup vs baseline: 1.8969x; 1.0332x over previous
#include <cuda_runtime.h>

#define DD 128
#define NMAX 50000
#define EMAX 800000
#define LAYERS 3
#define EPSV 1e-5f

// ---- scratch (no allocs allowed) ----
__device__ float g_m[NMAX * DD];     // m = h @ W
__device__ float g_agg[NMAX * DD];   // aggregated messages (pre-BN)
__device__ float g_dinv[NMAX];       // rsqrt(deg)
__device__ int   g_cnt[NMAX];        // in-edge count per dst (no self-loop)
__device__ int   g_off[NMAX];        // per-node segment start (unordered alloc)
__device__ int   g_cur[NMAX];        // scatter cursors
__device__ int   g_total;            // segment allocator
__device__ int   g_es[EMAX];         // dst-grouped src ids
__device__ float g_ew[EMAX];         // dst-grouped edge weights dinv[s]*dinv[t]
__device__ float g_sum[DD];
__device__ float g_sumsq[DD];
__device__ float g_scale[DD];
__device__ float g_shift[DD];

// ---------------- CSR construction (proven) ----------------
__global__ void zero_cnt_kernel(int n) {
    int i = blockIdx.x * blockDim.x + threadIdx.x;
    if (i < n) g_cnt[i] = 0;
    if (i == 0) g_total = 0;
}

__global__ void hist_kernel(const int* __restrict__ dst, int E) {
    int e = blockIdx.x * blockDim.x + threadIdx.x;
    if (e < E) atomicAdd(&g_cnt[dst[e]], 1);
}

__global__ void dinv_kernel(int n) {
    int i = blockIdx.x * blockDim.x + threadIdx.x;
    if (i < n) g_dinv[i] = rsqrtf((float)(g_cnt[i] + 1));  // +1 self-loop
}

__global__ void alloc_off_kernel(int n) {
    int i = blockIdx.x * blockDim.x + threadIdx.x;
    if (i >= n) return;
    int c = g_cnt[i];
    int pos = (c > 0) ? atomicAdd(&g_total, c) : 0;
    g_off[i] = pos;
    g_cur[i] = pos;
}

__global__ void edge_sort_kernel(const int* __restrict__ src,
                                 const int* __restrict__ dst, int E) {
    int e = blockIdx.x * blockDim.x + threadIdx.x;
    if (e >= E) return;
    int s = src[e], t = dst[e];
    int pos = atomicAdd(&g_cur[t], 1);
    g_es[pos] = s;
    g_ew[pos] = g_dinv[s] * g_dinv[t];
}

// ---------------- GEMM: m = act(h) @ W ----------------
// 64 rows x 128 cols per block, 256 threads, 8x4 register micro-tile.
// fused=1: input read applies BN scale/shift + ReLU of previous layer.
__global__ __launch_bounds__(256) void gemm_kernel(
    const float* __restrict__ x, int fused,
    const float* __restrict__ Wl, int n)
{
    const float* __restrict__ in = fused ? g_agg : x;
    __shared__ float hsT[32][64];      // [k][row] transposed tile
    __shared__ float ws[32][DD];       // [k][col]
    __shared__ float s_scale[DD], s_shift[DD];

    int tid = threadIdx.x;
    if (tid < DD) {
        s_scale[tid] = fused ? g_scale[tid] : 1.0f;
        s_shift[tid] = fused ? g_shift[tid] : 0.0f;
    }
    __syncthreads();

    int row0 = blockIdx.x * 64;
    int c4 = tid & 31;   // col quad (lane id)
    int rg = tid >> 5;   // row group (warp id)

    float acc[8][4];
#pragma unroll
    for (int r = 0; r < 8; r++)
#pragma unroll
        for (int c = 0; c < 4; c++) acc[r][c] = 0.0f;

    for (int kt = 0; kt < DD; kt += 32) {
        // h tile: 64 rows x 32 k, stored transposed.
        for (int q = tid; q < 512; q += 256) {
            int kq = q >> 6, row = q & 63;
            int gr = row0 + row;
            float4 v = make_float4(0.f, 0.f, 0.f, 0.f);
            if (gr < n)
                v = *(const float4*)(in + (size_t)gr * DD + kt + kq * 4);
            if (fused) {
                int k = kt + kq * 4;
                v.x = fmaxf(0.f, v.x * s_scale[k + 0] + s_shift[k + 0]);
                v.y = fmaxf(0.f, v.y * s_scale[k + 1] + s_shift[k + 1]);
                v.z = fmaxf(0.f, v.z * s_scale[k + 2] + s_shift[k + 2]);
                v.w = fmaxf(0.f, v.w * s_scale[k + 3] + s_shift[k + 3]);
            }
            hsT[kq * 4 + 0][row] = v.x;
            hsT[kq * 4 + 1][row] = v.y;
            hsT[kq * 4 + 2][row] = v.z;
            hsT[kq * 4 + 3][row] = v.w;
        }
        // W tile: 32 k x 128 cols, coalesced float4 loads.
        for (int q = tid; q < 1024; q += 256) {
            int r = q >> 5, cq = q & 31;
            *(float4*)&ws[r][cq * 4] =
                *(const float4*)(Wl + (size_t)(kt + r) * DD + cq * 4);
        }
        __syncthreads();
#pragma unroll
        for (int kk = 0; kk < 32; kk++) {
            float4 b = *(float4*)&ws[kk][c4 * 4];
            float4 a0 = *(float4*)&hsT[kk][rg * 8];
            float4 a1 = *(float4*)&hsT[kk][rg * 8 + 4];
            float a[8] = {a0.x, a0.y, a0.z, a0.w, a1.x, a1.y, a1.z, a1.w};
#pragma unroll
            for (int r = 0; r < 8; r++) {
                acc[r][0] += a[r] * b.x;
                acc[r][1] += a[r] * b.y;
                acc[r][2] += a[r] * b.z;
                acc[r][3] += a[r] * b.w;
            }
        }
        __syncthreads();
    }
#pragma unroll
    for (int r = 0; r < 8; r++) {
        int gr = row0 + rg * 8 + r;
        if (gr < n) {
            float4 v = make_float4(acc[r][0], acc[r][1], acc[r][2], acc[r][3]);
            *(float4*)(g_m + (size_t)gr * DD + c4 * 4) = v;
        }
    }
}

// ---------------- gather + fused BN stats ----------------
// grid-strided: each warp aggregates nodes, accumulating per-column
// sum/sumsq in registers; block-level smem reduce -> one atomicAdd/col/block.
__global__ __launch_bounds__(256) void gather_stats_kernel(int n) {
    __shared__ float s_sum[8][DD];
    __shared__ float s_sq[8][DD];

    int tid = threadIdx.x;
    int lane = tid & 31;
    int warp = tid >> 5;
    int gwarp = blockIdx.x * 8 + warp;
    int nwarps = gridDim.x * 8;
    const float4* __restrict__ m4 = (const float4*)g_m;

    float4 lsum = make_float4(0.f, 0.f, 0.f, 0.f);
    float4 lsq  = make_float4(0.f, 0.f, 0.f, 0.f);

    for (int node = gwarp; node < n; node += nwarps) {
        float di = g_dinv[node];
        float w0 = di * di;
        float4 acc = m4[(size_t)node * 32 + lane];
        acc.x *= w0; acc.y *= w0; acc.z *= w0; acc.w *= w0;

        int beg = g_off[node];
        int cnt = g_cnt[node];
        for (int i = 0; i < cnt; i++) {
            int s = g_es[beg + i];
            float w = g_ew[beg + i];
            float4 v = m4[(size_t)s * 32 + lane];
            acc.x += w * v.x;
            acc.y += w * v.y;
            acc.z += w * v.z;
            acc.w += w * v.w;
        }
        ((float4*)g_agg)[(size_t)node * 32 + lane] = acc;

        lsum.x += acc.x; lsum.y += acc.y; lsum.z += acc.z; lsum.w += acc.w;
        lsq.x += acc.x * acc.x; lsq.y += acc.y * acc.y;
        lsq.z += acc.z * acc.z; lsq.w += acc.w * acc.w;
    }

    *(float4*)&s_sum[warp][lane * 4] = lsum;
    *(float4*)&s_sq[warp][lane * 4]  = lsq;
    __syncthreads();

    if (tid < DD) {
        float a = 0.f, b = 0.f;
#pragma unroll
        for (int w = 0; w < 8; w++) {
            a += s_sum[w][tid];
            b += s_sq[w][tid];
        }
        atomicAdd(&g_sum[tid], a);
        atomicAdd(&g_sumsq[tid], b);
    }
}

// ---------------- batchnorm finalize ----------------
__global__ void zero_stats_kernel() {
    int d = threadIdx.x;
    g_sum[d] = 0.0f;
    g_sumsq[d] = 0.0f;
}

// GCN bias b cancels inside BN (mean shifts by b, variance unchanged) -> skip it.
__global__ void finalize_stats_kernel(const float* __restrict__ gamma,
                                      const float* __restrict__ beta, float inv_n) {
    int d = threadIdx.x;
    float mu = g_sum[d] * inv_n;
    float var = g_sumsq[d] * inv_n - mu * mu;
    float rstd = rsqrtf(var + EPSV);
    float sc = gamma[d] * rstd;
    g_scale[d] = sc;
    g_shift[d] = beta[d] - mu * sc;
}

// ---------------- final normalize + relu -> out ----------------
__global__ void norm_relu_kernel(float* __restrict__ out, int n) {
    int idx = blockIdx.x * blockDim.x + threadIdx.x;  // float4 index
    int total = n * (DD / 4);
    if (idx >= total) return;
    int c4 = (idx & 31) * 4;
    float4 v = reinterpret_cast<const float4*>(g_agg)[idx];
    float4 r;
    r.x = fmaxf(0.0f, v.x * g_scale[c4 + 0] + g_shift[c4 + 0]);
    r.y = fmaxf(0.0f, v.y * g_scale[c4 + 1] + g_shift[c4 + 1]);
    r.z = fmaxf(0.0f, v.z * g_scale[c4 + 2] + g_shift[c4 + 2]);
    r.w = fmaxf(0.0f, v.w * g_scale[c4 + 3] + g_shift[c4 + 3]);
    reinterpret_cast<float4*>(out)[idx] = r;
}

// ---------------- launcher ----------------
extern "C" void kernel_launch(void* const* d_in, const int* in_sizes, int n_in,
                              void* d_out, int out_size) {
    const float* x     = (const float*)d_in[0];
    const int*   ei    = (const int*)d_in[1];
    const float* W     = (const float*)d_in[2];
    // d_in[3] = b : mathematically absorbed by batchnorm, unused
    const float* gamma = (const float*)d_in[4];
    const float* beta  = (const float*)d_in[5];
    float* out = (float*)d_out;

    int n = in_sizes[0] / DD;
    int E = in_sizes[1] / 2;
    const int* src = ei;
    const int* dst = ei + E;

    // CSR build (once per launch)
    zero_cnt_kernel<<<(n + 255) / 256, 256>>>(n);
    hist_kernel<<<(E + 255) / 256, 256>>>(dst, E);
    dinv_kernel<<<(n + 255) / 256, 256>>>(n);
    alloc_off_kernel<<<(n + 255) / 256, 256>>>(n);
    edge_sort_kernel<<<(E + 255) / 256, 256>>>(src, dst, E);

    int elem4 = n * (DD / 4);
    for (int l = 0; l < LAYERS; l++) {
        // layer 0 reads x plain; layers 1,2 read g_agg with fused BN+ReLU
        gemm_kernel<<<(n + 63) / 64, 256>>>(x, (l == 0) ? 0 : 1,
                                            W + (size_t)l * DD * DD, n);
        zero_stats_kernel<<<1, DD>>>();
        gather_stats_kernel<<<512, 256>>>(n);
        finalize_stats_kernel<<<1, DD>>>(gamma + (size_t)l * DD,
                                         beta + (size_t)l * DD, 1.0f / (float)n);
    }
    norm_relu_kernel<<<(elem4 + 255) / 256, 256>>>(out, n);
}

// round 9
// speedup vs baseline: 1.9782x; 1.0429x over previous
#include <cuda_runtime.h>
#include <cstdint>

#define DD 128
#define NMAX 50000
#define EMAX 800000
#define LAYERS 3
#define EPSV 1e-5f
#define PADK 136   // padded row stride for [k][*] smem tiles (bank = 8k+idx mod 32)

// ---- scratch (no allocs allowed) ----
__device__ float g_m[NMAX * DD];     // m = h @ W
__device__ float g_agg[NMAX * DD];   // aggregated messages (pre-BN)
__device__ float g_dinv[NMAX];       // rsqrt(deg)
__device__ int   g_cnt[NMAX];        // in-edge count per dst (no self-loop)
__device__ int   g_off[NMAX];        // per-node segment start (unordered alloc)
__device__ int   g_cur[NMAX];        // scatter cursors
__device__ int   g_total;            // segment allocator
__device__ int   g_es[EMAX];         // dst-grouped src ids
__device__ float g_ew[EMAX];         // dst-grouped edge weights dinv[s]*dinv[t]
__device__ float g_sum[DD];
__device__ float g_sumsq[DD];
__device__ float g_scale[DD];
__device__ float g_shift[DD];

// ---------------- CSR construction (proven) ----------------
__global__ void zero_cnt_kernel(int n) {
    int i = blockIdx.x * blockDim.x + threadIdx.x;
    if (i < n) g_cnt[i] = 0;
    if (i == 0) g_total = 0;
}

__global__ void hist_kernel(const int* __restrict__ dst, int E) {
    int e = blockIdx.x * blockDim.x + threadIdx.x;
    if (e < E) atomicAdd(&g_cnt[dst[e]], 1);
}

__global__ void dinv_kernel(int n) {
    int i = blockIdx.x * blockDim.x + threadIdx.x;
    if (i < n) g_dinv[i] = rsqrtf((float)(g_cnt[i] + 1));  // +1 self-loop
}

__global__ void alloc_off_kernel(int n) {
    int i = blockIdx.x * blockDim.x + threadIdx.x;
    if (i >= n) return;
    int c = g_cnt[i];
    int pos = (c > 0) ? atomicAdd(&g_total, c) : 0;
    g_off[i] = pos;
    g_cur[i] = pos;
}

__global__ void edge_sort_kernel(const int* __restrict__ src,
                                 const int* __restrict__ dst, int E) {
    int e = blockIdx.x * blockDim.x + threadIdx.x;
    if (e >= E) return;
    int s = src[e], t = dst[e];
    int pos = atomicAdd(&g_cur[t], 1);
    g_es[pos] = s;
    g_ew[pos] = g_dinv[s] * g_dinv[t];
}

// ---------------- tf32 helpers ----------------
__device__ __forceinline__ void split_tf32(float v, uint32_t& hi, uint32_t& lo) {
    uint32_t h;
    asm("cvt.rna.tf32.f32 %0, %1;" : "=r"(h) : "f"(v));
    float l = v - __uint_as_float(h);
    uint32_t lw;
    asm("cvt.rna.tf32.f32 %0, %1;" : "=r"(lw) : "f"(l));
    hi = h; lo = lw;
}

__device__ __forceinline__ void mma_tf32(float* c, uint32_t a0, uint32_t a1,
                                         uint32_t a2, uint32_t a3,
                                         uint32_t b0, uint32_t b1) {
    asm volatile(
        "mma.sync.aligned.m16n8k8.row.col.f32.tf32.tf32.f32 "
        "{%0,%1,%2,%3}, {%4,%5,%6,%7}, {%8,%9}, {%0,%1,%2,%3};"
        : "+f"(c[0]), "+f"(c[1]), "+f"(c[2]), "+f"(c[3])
        : "r"(a0), "r"(a1), "r"(a2), "r"(a3), "r"(b0), "r"(b1));
}

// ---------------- GEMM (tensor core, 3xTF32): m = act(h) @ W ----------------
// 128 rows x 128 cols per block, 256 threads (8 warps, 4x2 warp grid).
// Warp tile: 32 rows x 64 cols = 2 m-tiles x 8 n-tiles of m16n8k8.
__global__ __launch_bounds__(256) void gemm_tc_kernel(
    const float* __restrict__ x, int fused,
    const float* __restrict__ Wl, int n)
{
    const float* __restrict__ in = fused ? g_agg : x;
    __shared__ float aT[32][PADK];     // [k][row] transposed A chunk
    __shared__ float bs[32][PADK];     // [k][col] W chunk
    __shared__ float s_scale[DD], s_shift[DD];

    int tid = threadIdx.x;
    if (tid < DD) {
        s_scale[tid] = fused ? g_scale[tid] : 1.0f;
        s_shift[tid] = fused ? g_shift[tid] : 0.0f;
    }
    __syncthreads();

    int lane = tid & 31;
    int warp = tid >> 5;
    int warp_m = warp >> 1;            // 0..3  -> rows warp_m*32 .. +31
    int warp_n = warp & 1;             // 0..1  -> cols warp_n*64 .. +63
    int row0 = blockIdx.x * 128;

    float acc[2][8][4];
#pragma unroll
    for (int mt = 0; mt < 2; mt++)
#pragma unroll
        for (int nt = 0; nt < 8; nt++)
#pragma unroll
            for (int i = 0; i < 4; i++) acc[mt][nt][i] = 0.0f;

    int lq = lane >> 2;   // 0..7
    int lr = lane & 3;    // 0..3

    for (int kt = 0; kt < DD; kt += 32) {
        // A chunk: 128 rows x 32 k, stored transposed. 1024 float4 gmem loads.
        for (int q = tid; q < 1024; q += 256) {
            int kq = q >> 7, row = q & 127;     // lanes -> consecutive rows
            int gr = row0 + row;
            float4 v = make_float4(0.f, 0.f, 0.f, 0.f);
            if (gr < n)
                v = *(const float4*)(in + (size_t)gr * DD + kt + kq * 4);
            if (fused) {
                int k = kt + kq * 4;
                v.x = fmaxf(0.f, v.x * s_scale[k + 0] + s_shift[k + 0]);
                v.y = fmaxf(0.f, v.y * s_scale[k + 1] + s_shift[k + 1]);
                v.z = fmaxf(0.f, v.z * s_scale[k + 2] + s_shift[k + 2]);
                v.w = fmaxf(0.f, v.w * s_scale[k + 3] + s_shift[k + 3]);
            }
            aT[kq * 4 + 0][row] = v.x;
            aT[kq * 4 + 1][row] = v.y;
            aT[kq * 4 + 2][row] = v.z;
            aT[kq * 4 + 3][row] = v.w;
        }
        // W chunk: 32 k x 128 cols, coalesced float4 loads.
        for (int q = tid; q < 1024; q += 256) {
            int r = q >> 5, cq = q & 31;
            *(float4*)&bs[r][cq * 4] =
                *(const float4*)(Wl + (size_t)(kt + r) * DD + cq * 4);
        }
        __syncthreads();

#pragma unroll
        for (int ks = 0; ks < 4; ks++) {
            int kk = ks * 8;
            // A fragments for 2 m-tiles, split hi/lo
            uint32_t ah[2][4], al[2][4];
#pragma unroll
            for (int mt = 0; mt < 2; mt++) {
                int rb = warp_m * 32 + mt * 16 + lq;
                float f0 = aT[kk + lr][rb];
                float f1 = aT[kk + lr][rb + 8];
                float f2 = aT[kk + lr + 4][rb];
                float f3 = aT[kk + lr + 4][rb + 8];
                split_tf32(f0, ah[mt][0], al[mt][0]);
                split_tf32(f1, ah[mt][1], al[mt][1]);
                split_tf32(f2, ah[mt][2], al[mt][2]);
                split_tf32(f3, ah[mt][3], al[mt][3]);
            }
#pragma unroll
            for (int nt = 0; nt < 8; nt++) {
                int cb = warp_n * 64 + nt * 8 + lq;
                float g0 = bs[kk + lr][cb];
                float g1 = bs[kk + lr + 4][cb];
                uint32_t bh0, bl0, bh1, bl1;
                split_tf32(g0, bh0, bl0);
                split_tf32(g1, bh1, bl1);
#pragma unroll
                for (int mt = 0; mt < 2; mt++) {
                    mma_tf32(acc[mt][nt], ah[mt][0], ah[mt][1], ah[mt][2], ah[mt][3], bh0, bh1);
                    mma_tf32(acc[mt][nt], al[mt][0], al[mt][1], al[mt][2], al[mt][3], bh0, bh1);
                    mma_tf32(acc[mt][nt], ah[mt][0], ah[mt][1], ah[mt][2], ah[mt][3], bl0, bl1);
                }
            }
        }
        __syncthreads();
    }

    // epilogue: c0,c1 at (row, 2c), (row, 2c+1); c2,c3 at row+8
#pragma unroll
    for (int mt = 0; mt < 2; mt++) {
        int gr0 = row0 + warp_m * 32 + mt * 16 + lq;
#pragma unroll
        for (int nt = 0; nt < 8; nt++) {
            int gc = warp_n * 64 + nt * 8 + lr * 2;
            if (gr0 < n)
                *(float2*)(g_m + (size_t)gr0 * DD + gc) =
                    make_float2(acc[mt][nt][0], acc[mt][nt][1]);
            if (gr0 + 8 < n)
                *(float2*)(g_m + (size_t)(gr0 + 8) * DD + gc) =
                    make_float2(acc[mt][nt][2], acc[mt][nt][3]);
        }
    }
}

// ---------------- gather + fused BN stats (round-7 proven) ----------------
__global__ __launch_bounds__(256) void gather_stats_kernel(int n) {
    __shared__ float s_sum[8][DD];
    __shared__ float s_sq[8][DD];

    int tid = threadIdx.x;
    int lane = tid & 31;
    int warp = tid >> 5;
    int gwarp = blockIdx.x * 8 + warp;
    int nwarps = gridDim.x * 8;
    const float4* __restrict__ m4 = (const float4*)g_m;

    float4 lsum = make_float4(0.f, 0.f, 0.f, 0.f);
    float4 lsq  = make_float4(0.f, 0.f, 0.f, 0.f);

    for (int node = gwarp; node < n; node += nwarps) {
        float di = g_dinv[node];
        float w0 = di * di;
        float4 acc = m4[(size_t)node * 32 + lane];
        acc.x *= w0; acc.y *= w0; acc.z *= w0; acc.w *= w0;

        int beg = g_off[node];
        int cnt = g_cnt[node];
        for (int i = 0; i < cnt; i++) {
            int s = g_es[beg + i];
            float w = g_ew[beg + i];
            float4 v = m4[(size_t)s * 32 + lane];
            acc.x += w * v.x;
            acc.y += w * v.y;
            acc.z += w * v.z;
            acc.w += w * v.w;
        }
        ((float4*)g_agg)[(size_t)node * 32 + lane] = acc;

        lsum.x += acc.x; lsum.y += acc.y; lsum.z += acc.z; lsum.w += acc.w;
        lsq.x += acc.x * acc.x; lsq.y += acc.y * acc.y;
        lsq.z += acc.z * acc.z; lsq.w += acc.w * acc.w;
    }

    *(float4*)&s_sum[warp][lane * 4] = lsum;
    *(float4*)&s_sq[warp][lane * 4]  = lsq;
    __syncthreads();

    if (tid < DD) {
        float a = 0.f, b = 0.f;
#pragma unroll
        for (int w = 0; w < 8; w++) {
            a += s_sum[w][tid];
            b += s_sq[w][tid];
        }
        atomicAdd(&g_sum[tid], a);
        atomicAdd(&g_sumsq[tid], b);
    }
}

// ---------------- batchnorm finalize ----------------
__global__ void zero_stats_kernel() {
    int d = threadIdx.x;
    g_sum[d] = 0.0f;
    g_sumsq[d] = 0.0f;
}

// GCN bias b cancels inside BN (mean shifts by b, variance unchanged) -> skip it.
__global__ void finalize_stats_kernel(const float* __restrict__ gamma,
                                      const float* __restrict__ beta, float inv_n) {
    int d = threadIdx.x;
    float mu = g_sum[d] * inv_n;
    float var = g_sumsq[d] * inv_n - mu * mu;
    float rstd = rsqrtf(var + EPSV);
    float sc = gamma[d] * rstd;
    g_scale[d] = sc;
    g_shift[d] = beta[d] - mu * sc;
}

// ---------------- final normalize + relu -> out ----------------
__global__ void norm_relu_kernel(float* __restrict__ out, int n) {
    int idx = blockIdx.x * blockDim.x + threadIdx.x;  // float4 index
    int total = n * (DD / 4);
    if (idx >= total) return;
    int c4 = (idx & 31) * 4;
    float4 v = reinterpret_cast<const float4*>(g_agg)[idx];
    float4 r;
    r.x = fmaxf(0.0f, v.x * g_scale[c4 + 0] + g_shift[c4 + 0]);
    r.y = fmaxf(0.0f, v.y * g_scale[c4 + 1] + g_shift[c4 + 1]);
    r.z = fmaxf(0.0f, v.z * g_scale[c4 + 2] + g_shift[c4 + 2]);
    r.w = fmaxf(0.0f, v.w * g_scale[c4 + 3] + g_shift[c4 + 3]);
    reinterpret_cast<float4*>(out)[idx] = r;
}

// ---------------- launcher ----------------
extern "C" void kernel_launch(void* const* d_in, const int* in_sizes, int n_in,
                              void* d_out, int out_size) {
    const float* x     = (const float*)d_in[0];
    const int*   ei    = (const int*)d_in[1];
    const float* W     = (const float*)d_in[2];
    // d_in[3] = b : mathematically absorbed by batchnorm, unused
    const float* gamma = (const float*)d_in[4];
    const float* beta  = (const float*)d_in[5];
    float* out = (float*)d_out;

    int n = in_sizes[0] / DD;
    int E = in_sizes[1] / 2;
    const int* src = ei;
    const int* dst = ei + E;

    // CSR build (once per launch)
    zero_cnt_kernel<<<(n + 255) / 256, 256>>>(n);
    hist_kernel<<<(E + 255) / 256, 256>>>(dst, E);
    dinv_kernel<<<(n + 255) / 256, 256>>>(n);
    alloc_off_kernel<<<(n + 255) / 256, 256>>>(n);
    edge_sort_kernel<<<(E + 255) / 256, 256>>>(src, dst, E);

    int elem4 = n * (DD / 4);
    for (int l = 0; l < LAYERS; l++) {
        gemm_tc_kernel<<<(n + 127) / 128, 256>>>(x, (l == 0) ? 0 : 1,
                                                 W + (size_t)l * DD * DD, n);
        zero_stats_kernel<<<1, DD>>>();
        gather_stats_kernel<<<512, 256>>>(n);
        finalize_stats_kernel<<<1, DD>>>(gamma + (size_t)l * DD,
                                         beta + (size_t)l * DD, 1.0f / (float)n);
    }
    norm_relu_kernel<<<(elem4 + 255) / 256, 256>>>(out, n);
}